// round 5
// baseline (speedup 1.0000x reference)
#include <cuda_runtime.h>
#include <cfloat>
#include <cstdint>

// Problem constants (fixed shapes from reference)
#define PB   2
#define PH   4
#define PLQ  512
#define PLKV 512
#define PD   64
#define PBH  (PB * PH)     // 8
#define TQ   8             // q-rows per block in main kernel

// Scratch for projected q/k (allocation-free rule: __device__ globals)
__device__ float g_qp[PBH * PLQ * PD];   // qp + b_concat folded in
__device__ float g_kp[PBH * PLKV * PD];

__device__ __forceinline__ float tanh_fast(float x) {
    float r;
    asm("tanh.approx.f32 %0, %1;" : "=f"(r) : "f"(x));
    return r;
}

// ---------------------------------------------------------------------------
// Projection: qp[r,e] = sum_d Q[r,d] * W[e, d]        + bias[e]   (r < BH*LQ)
//             kp[r,e] = sum_d K[r,d] * W[e, D + d]               (r >= BH*LQ)
// W_concat is (D, 2D) row-major.
// One 64-thread sub-group per row; 4 rows per 256-thread block.
// ---------------------------------------------------------------------------
__global__ __launch_bounds__(256) void proj_kernel(
    const float* __restrict__ Q, const float* __restrict__ K,
    const float* __restrict__ W, const float* __restrict__ bias)
{
    __shared__ float sh[4][PD];
    const int sub = threadIdx.x >> 6;           // row within block (0..3)
    const int e   = threadIdx.x & 63;
    const int r   = blockIdx.x * 4 + sub;       // global row, 0..2*BH*LQ-1

    const bool isQ = (r < PBH * PLQ);
    const int  rr  = isQ ? r : (r - PBH * PLQ);
    const float* in = (isQ ? Q : K) + (size_t)rr * PD;

    sh[sub][e] = in[e];
    __syncthreads();

    const float4* w4 = (const float4*)(W + (size_t)e * (2 * PD) + (isQ ? 0 : PD));
    const float4* s4 = (const float4*)sh[sub];

    float acc = isQ ? bias[e] : 0.0f;
#pragma unroll
    for (int i = 0; i < PD / 4; i++) {
        float4 wv = w4[i];
        float4 sv = s4[i];
        acc += wv.x * sv.x;
        acc += wv.y * sv.y;
        acc += wv.z * sv.z;
        acc += wv.w * sv.w;
    }

    float* dst = isQ ? g_qp : g_kp;
    dst[(size_t)rr * PD + e] = acc;
}

// ---------------------------------------------------------------------------
// Main kernel: one block = (bh, 8 consecutive q rows), all 512 k.
//   Phase 1: logits[q][k] = sum_e w[e]*tanh(qp[q,e] + kp[k,e])   (kp in regs)
//   Phase 2: per-warp masked softmax over each q row, write weights.
// Grid: BH * (LQ/TQ) = 512 blocks, 256 threads.
// ---------------------------------------------------------------------------
__global__ __launch_bounds__(256) void attn_kernel(
    const int* __restrict__ mask,
    const float* __restrict__ w_logit,
    float* __restrict__ out)
{
    __shared__ float qp_s[TQ][PD];       // 2 KB
    __shared__ float ws[PD];             // 256 B
    __shared__ float logits_s[TQ][PLKV]; // 16 KB

    const int bh  = blockIdx.x / (PLQ / TQ);
    const int qt  = blockIdx.x % (PLQ / TQ);
    const int q0  = qt * TQ;
    const int tid = threadIdx.x;

    // Load qp tile (TQ*D = 512 floats) and w_logit into shared
    const float* qpbase = g_qp + ((size_t)bh * PLQ + q0) * PD;
    for (int i = tid; i < TQ * PD; i += 256)
        ((float*)qp_s)[i] = qpbase[i];
    if (tid < PD) ws[tid] = w_logit[tid];
    __syncthreads();

    const float* kpbase = g_kp + (size_t)bh * PLKV * PD;

    // ---- Phase 1: logits ----
    for (int c = 0; c < PLKV; c += 256) {
        const int k = c + tid;

        // kp row for this thread's k -> registers
        float kr[PD];
        const float4* kp4 = (const float4*)(kpbase + (size_t)k * PD);
#pragma unroll
        for (int i = 0; i < PD / 4; i++) {
            float4 v = kp4[i];
            kr[4 * i + 0] = v.x;
            kr[4 * i + 1] = v.y;
            kr[4 * i + 2] = v.z;
            kr[4 * i + 3] = v.w;
        }

        for (int q = 0; q < TQ; q++) {
            const float4* qp4 = (const float4*)qp_s[q];
            const float4* w4  = (const float4*)ws;
            float acc0 = 0.0f, acc1 = 0.0f;
#pragma unroll
            for (int e4 = 0; e4 < PD / 4; e4++) {
                float4 qv = qp4[e4];   // broadcast LDS.128
                float4 wv = w4[e4];    // broadcast LDS.128
                acc0 += wv.x * tanh_fast(qv.x + kr[4 * e4 + 0]);
                acc1 += wv.y * tanh_fast(qv.y + kr[4 * e4 + 1]);
                acc0 += wv.z * tanh_fast(qv.z + kr[4 * e4 + 2]);
                acc1 += wv.w * tanh_fast(qv.w + kr[4 * e4 + 3]);
            }
            logits_s[q][k] = acc0 + acc1;
        }
    }
    __syncthreads();

    // ---- Phase 2: masked softmax, one warp per q row ----
    const int w    = tid >> 5;
    const int lane = tid & 31;
    const int qg   = q0 + w;
    const int b    = bh / PH;
    const int* mrow = mask + ((size_t)b * PLQ + qg) * PLKV;

    float m_val = -FLT_MAX, m_raw = -FLT_MAX;
    int anyv = 0;
    for (int j = lane; j < PLKV; j += 32) {
        float l = logits_s[w][j];
        int   v = mrow[j] != 0;
        anyv |= v;
        m_raw = fmaxf(m_raw, l);
        if (v) m_val = fmaxf(m_val, l);
    }
#pragma unroll
    for (int o = 16; o; o >>= 1) {
        m_val = fmaxf(m_val, __shfl_xor_sync(0xffffffffu, m_val, o));
        m_raw = fmaxf(m_raw, __shfl_xor_sync(0xffffffffu, m_raw, o));
    }
    const bool any = __ballot_sync(0xffffffffu, anyv) != 0;
    const float M = any ? m_val : m_raw;

    float s = 0.0f;
    for (int j = lane; j < PLKV; j += 32) {
        float l = logits_s[w][j];
        bool  v = (!any) || (mrow[j] != 0);
        float p = v ? __expf(l - M) : 0.0f;
        logits_s[w][j] = p;
        s += p;
    }
#pragma unroll
    for (int o = 16; o; o >>= 1)
        s += __shfl_xor_sync(0xffffffffu, s, o);
    const float inv = 1.0f / s;

    float* orow = out + ((size_t)bh * PLQ + qg) * PLKV;
    for (int j = lane; j < PLKV; j += 32)
        orow[j] = logits_s[w][j] * inv;
}

// ---------------------------------------------------------------------------
// Inputs (metadata order): queries, keys, values(unused), mask, W_concat,
// b_concat, w_logit, b_logit(unused: softmax shift-invariant)
// Mask is delivered as int32 (harness converts bool; supported dtypes are
// float32/int32/bfloat16 per the stub header).
// ---------------------------------------------------------------------------
extern "C" void kernel_launch(void* const* d_in, const int* in_sizes, int n_in,
                              void* d_out, int out_size)
{
    const float* Q    = (const float*)d_in[0];
    const float* K    = (const float*)d_in[1];
    const int*   mask = (const int*)d_in[3];
    const float* W    = (const float*)d_in[4];
    const float* bc   = (const float*)d_in[5];
    const float* wl   = (const float*)d_in[6];
    float*       out  = (float*)d_out;

    // 2 * BH * LQ rows / 4 rows per block
    proj_kernel<<<(2 * PBH * PLQ) / 4, 256>>>(Q, K, W, bc);
    attn_kernel<<<PBH * (PLQ / TQ), 256>>>(mask, wl, out);
}